// round 7
// baseline (speedup 1.0000x reference)
#include <cuda_runtime.h>
#include <cstdint>

#define THREADS 128
#define CPB     128
#define STAGES  4
#define PRED_F  (CPB * 30)        // 3840 floats
#define TARG_F  (CPB * 25)        // 3200 floats
#define PRED_B  (PRED_F * 4)      // 15360 bytes (16-mult)
#define TARG_B  (TARG_F * 4)      // 12800 bytes (16-mult)
#define MAX_PART 2048

__device__ float g_partials[MAX_PART];
__device__ unsigned int g_count = 0;   // wraps to 0 each replay via atomicInc

__device__ __forceinline__ unsigned smem_u32(const void* p) {
    return (unsigned)__cvta_generic_to_shared(p);
}
__device__ __forceinline__ void mbar_init(unsigned a, unsigned cnt) {
    asm volatile("mbarrier.init.shared.b64 [%0], %1;" :: "r"(a), "r"(cnt) : "memory");
}
__device__ __forceinline__ void mbar_expect_tx(unsigned a, unsigned bytes) {
    asm volatile("mbarrier.arrive.expect_tx.shared.b64 _, [%0], %1;"
                 :: "r"(a), "r"(bytes) : "memory");
}
__device__ __forceinline__ void bulk_g2s(unsigned dst, const void* src,
                                         unsigned bytes, unsigned mbar) {
    asm volatile(
        "cp.async.bulk.shared::cluster.global.mbarrier::complete_tx::bytes "
        "[%0], [%1], %2, [%3];"
        :: "r"(dst), "l"(src), "r"(bytes), "r"(mbar) : "memory");
}
__device__ __forceinline__ void mbar_wait(unsigned a, unsigned parity) {
    asm volatile(
        "{\n\t"
        ".reg .pred P;\n\t"
        "WL_%=:\n\t"
        "mbarrier.try_wait.parity.acquire.cta.shared::cta.b64 P, [%0], %1, 0x989680;\n\t"
        "@P bra WD_%=;\n\t"
        "bra WL_%=;\n\t"
        "WD_%=:\n\t"
        "}"
        :: "r"(a), "r"(parity) : "memory");
}

// per-cell loss (indices relative to cell base)
__device__ __forceinline__ float cell_loss(const float* P, const float* T) {
    float c1 = P[4], c2 = P[9], c = T[4];
    bool present = (c == 1.0f);
    bool r1 = (c1 > c2);
    if (present) {
        float dobj = (r1 ? c1 : c2) - c;
        float loss = dobj * dobj;
        float cls = 0.0f;
        #pragma unroll
        for (int i = 0; i < 20; ++i) {
            float d = P[10 + i] - T[5 + i];
            cls = fmaf(d, d, cls);
        }
        int o = r1 ? 0 : 5;
        float box = 0.0f;
        #pragma unroll
        for (int i = 0; i < 2; ++i) {
            float d = P[o + i] - T[i];
            box = fmaf(d, d, box);
        }
        #pragma unroll
        for (int i = 0; i < 2; ++i) {
            float d = sqrtf(P[o + 2 + i]) - sqrtf(T[2 + i]);
            box = fmaf(d, d, box);
        }
        return loss + cls + 5.0f * box;
    }
    return 0.5f * fmaf(c1, c1, c2 * c2);
}

__global__ __launch_bounds__(THREADS) void yolo_loss_kernel(
    const float* __restrict__ pred,   // [n_cells, 30]
    const float* __restrict__ targ,   // [n_cells, 25]
    long n_cells,
    long n_full,                      // full 128-cell chunks
    float* __restrict__ out)
{
    __shared__ __align__(16) float sP[STAGES][PRED_F];   // 4 x 15360 B
    __shared__ __align__(16) float sT[STAGES][TARG_F];   // 4 x 12800 B
    __shared__ __align__(8)  unsigned long long full_bar[STAGES];

    const int tid = threadIdx.x;
    const long grid = gridDim.x;

    unsigned bar[STAGES];
    #pragma unroll
    for (int s = 0; s < STAGES; ++s) bar[s] = smem_u32(&full_bar[s]);

    if (tid == 0) {
        #pragma unroll
        for (int s = 0; s < STAGES; ++s) mbar_init(bar[s], 1);
    }
    __syncthreads();

    // ---- prologue: fill all STAGES slots via TMA bulk ----
    if (tid == 0) {
        #pragma unroll
        for (int s = 0; s < STAGES; ++s) {
            long ch = (long)blockIdx.x + (long)s * grid;
            if (ch < n_full) {
                mbar_expect_tx(bar[s], PRED_B + TARG_B);
                bulk_g2s(smem_u32(sP[s]), pred + ch * PRED_F, PRED_B, bar[s]);
                bulk_g2s(smem_u32(sT[s]), targ + ch * TARG_F, TARG_B, bar[s]);
            }
        }
    }

    float acc = 0.0f;
    long chunk = blockIdx.x;
    int it = 0;

    while (chunk < n_full) {
        int slot = it & (STAGES - 1);
        unsigned parity = (unsigned)((it >> 2) & 1);

        mbar_wait(bar[slot], parity);      // chunk resident + acquire

        acc += cell_loss(sP[slot] + tid * 30, sT[slot] + tid * 25);

        __syncthreads();                   // all lanes done reading slot

        // refill this slot with chunk + STAGES*grid
        long nc = chunk + (long)STAGES * grid;
        if (tid == 0 && nc < n_full) {
            mbar_expect_tx(bar[slot], PRED_B + TARG_B);
            bulk_g2s(smem_u32(sP[slot]), pred + nc * PRED_F, PRED_B, bar[slot]);
            bulk_g2s(smem_u32(sT[slot]), targ + nc * TARG_F, TARG_B, bar[slot]);
        }

        chunk += grid;
        ++it;
    }

    // ---- ragged tail (cells beyond n_full*CPB): block 0, direct loads ----
    if (blockIdx.x == 0) {
        for (long cell = n_full * CPB + tid; cell < n_cells; cell += THREADS) {
            float Pl[30], Tl[25];
            #pragma unroll
            for (int i = 0; i < 30; ++i) Pl[i] = __ldg(pred + cell * 30 + i);
            #pragma unroll
            for (int i = 0; i < 25; ++i) Tl[i] = __ldg(targ + cell * 25 + i);
            acc += cell_loss(Pl, Tl);
        }
    }

    // ---- block reduction ----
    #pragma unroll
    for (int off = 16; off > 0; off >>= 1)
        acc += __shfl_xor_sync(0xFFFFFFFFu, acc, off);

    __shared__ float wsum[THREADS / 32];
    const int wid = tid >> 5, lid = tid & 31;
    if (lid == 0) wsum[wid] = acc;
    __syncthreads();

    __shared__ int s_last;
    if (tid == 0) {
        g_partials[blockIdx.x] = wsum[0] + wsum[1] + wsum[2] + wsum[3];
        __threadfence();
        unsigned old = atomicInc(&g_count, gridDim.x - 1);
        s_last = (old == gridDim.x - 1) ? 1 : 0;
    }
    __syncthreads();

    if (s_last) {
        __threadfence();
        double d = 0.0;
        for (int i = tid; i < (int)gridDim.x; i += THREADS)
            d += (double)__ldcg(&g_partials[i]);
        #pragma unroll
        for (int off = 16; off > 0; off >>= 1)
            d += __shfl_xor_sync(0xFFFFFFFFu, d, off);
        __shared__ double dsum[THREADS / 32];
        if (lid == 0) dsum[wid] = d;
        __syncthreads();
        if (tid == 0)
            out[0] = (float)(dsum[0] + dsum[1] + dsum[2] + dsum[3]);
    }
}

extern "C" void kernel_launch(void* const* d_in, const int* in_sizes, int n_in,
                              void* d_out, int out_size) {
    const float* pred = (const float*)d_in[0];   // [B, 1470]
    const float* targ = (const float*)d_in[1];   // [B, 1225]
    float* out = (float*)d_out;

    long B = (long)in_sizes[0] / 1470;
    long n_cells = B * 49;
    long n_full = n_cells / CPB;                 // exact for B=16384 (6272)

    long blocks = 148L * 2;                      // 112.7 KB smem -> 2 blocks/SM
    if (blocks > n_full) blocks = n_full;
    if (blocks < 1) blocks = 1;
    if (blocks > MAX_PART) blocks = MAX_PART;

    yolo_loss_kernel<<<(unsigned)blocks, THREADS>>>(pred, targ, n_cells, n_full, out);
}